// round 14
// baseline (speedup 1.0000x reference)
#include <cuda_runtime.h>
#include <cstdint>

#define N_PRE    50000
#define VEC_DIM  300        // 75 float4
#define HIDDEN   128        // 32 float4
#define IN_SIZE  50000
#define OUT_DIM  428        // 107 float4
#define N_TOKENS (64 * 200)
#define NBLK     (148 * 16) // 2368 persistent blocks, grid-stride over tokens

static __device__ __forceinline__ uint64_t mk_policy_evict_last() {
    uint64_t pol;
    asm volatile("createpolicy.fractional.L2::evict_last.b64 %0, 1.0;"
                 : "=l"(pol));
    return pol;
}
static __device__ __forceinline__ float ldg_el_f32(const float* p, uint64_t pol) {
    float v;
    asm volatile("ld.global.nc.L2::cache_hint.f32 %0, [%1], %2;"
                 : "=f"(v) : "l"(p), "l"(pol));
    return v;
}
static __device__ __forceinline__ float4 ldg_el_f128(const float4* p, uint64_t pol) {
    float4 v;
    asm volatile("ld.global.nc.L2::cache_hint.v4.f32 {%0,%1,%2,%3}, [%4], %5;"
                 : "=f"(v.x), "=f"(v.y), "=f"(v.z), "=f"(v.w)
                 : "l"(p), "l"(pol));
    return v;
}
static __device__ __forceinline__ void stg_cs_f128(float4* p, float4 v) {
    asm volatile("st.global.cs.v4.f32 [%0], {%1,%2,%3,%4};"
                 :: "l"(p), "f"(v.x), "f"(v.y), "f"(v.z), "f"(v.w) : "memory");
}

// Persistent blocks: each 128-thread block grid-strides over tokens, running
// the R11 per-token body (best so far) each iteration. No per-token block
// launch/drain; load streams of successive tokens overlap inside one block.
__global__ __launch_bounds__(128) void encoder_kernel(
    const int*    __restrict__ tokens,    // [N_TOKENS]
    const float4* __restrict__ vectors4,  // [N_PRE * 75]
    const float*  __restrict__ W,         // [HIDDEN, IN_SIZE]
    const float4* __restrict__ b4,        // [32]
    float4*       __restrict__ out4)      // [N_TOKENS * 107]
{
    const int tid = threadIdx.x;
    const uint64_t pol = mk_policy_evict_last();
    const float4 bb = __ldg(&b4[tid & 31]);     // b chunk for this lane id

    for (int t = blockIdx.x; t < N_TOKENS; t += NBLK) {
        const int tok = __ldg(&tokens[t]);
        float4* orow = out4 + (size_t)t * (OUT_DIM / 4);

        if (tok < N_PRE) {
            const float4* vrow = vectors4 + (size_t)tok * (VEC_DIM / 4);
            if (tid < 75) {
                float4 v = ldg_el_f128(&vrow[tid], pol);
                stg_cs_f128(&orow[tid], v);
            }
            if (tid < 32) {
                stg_cs_f128(&orow[75 + tid], bb);
            }
        } else {
            const float4 z = make_float4(0.f, 0.f, 0.f, 0.f);
            if (tid < 75) stg_cs_f128(&orow[tid], z);
            if (tid < 32) {
                const int c = tok - N_PRE;
                const float* Wc = W + c + (size_t)(4 * tid) * IN_SIZE;
                float w0 = ldg_el_f32(Wc, pol);
                float w1 = ldg_el_f32(Wc + (size_t)IN_SIZE, pol);
                float w2 = ldg_el_f32(Wc + (size_t)2 * IN_SIZE, pol);
                float w3 = ldg_el_f32(Wc + (size_t)3 * IN_SIZE, pol);
                float4 h = make_float4(bb.x + w0, bb.y + w1,
                                       bb.z + w2, bb.w + w3);
                stg_cs_f128(&orow[75 + tid], h);
            }
        }
    }
}

extern "C" void kernel_launch(void* const* d_in, const int* in_sizes, int n_in,
                              void* d_out, int out_size)
{
    // metadata order: tokens (int32), vectors (f32), W (f32), b (f32)
    const int*    tokens  = (const int*)   d_in[0];
    const float4* vectors = (const float4*)d_in[1];
    const float*  W       = (const float*) d_in[2];
    const float4* b       = (const float4*)d_in[3];
    float4*       out     = (float4*)      d_out;

    encoder_kernel<<<NBLK, 128>>>(tokens, vectors, W, b, out);
}

// round 15
// speedup vs baseline: 1.0227x; 1.0227x over previous
#include <cuda_runtime.h>
#include <cstdint>

#define N_PRE    50000
#define VEC_DIM  300        // 75 float4
#define HIDDEN   128        // 32 float4
#define IN_SIZE  50000
#define OUT_DIM  428        // 107 float4
#define N_TOKENS (64 * 200)

static __device__ __forceinline__ uint64_t mk_policy_evict_last() {
    uint64_t pol;
    asm volatile("createpolicy.fractional.L2::evict_last.b64 %0, 1.0;"
                 : "=l"(pol));
    return pol;
}
static __device__ __forceinline__ float ldg_el_f32(const float* p, uint64_t pol) {
    float v;
    asm volatile("ld.global.nc.L2::cache_hint.f32 %0, [%1], %2;"
                 : "=f"(v) : "l"(p), "l"(pol));
    return v;
}
static __device__ __forceinline__ void stg_cs_f128(float4* p, float4 v) {
    asm volatile("st.global.cs.v4.f32 [%0], {%1,%2,%3,%4};"
                 :: "l"(p), "f"(v.x), "f"(v.y), "f"(v.z), "f"(v.w) : "memory");
}

// R11 champion structure, with the L2 evict_last policy narrowed to ONLY the
// scattered W gather (the expensive, reused-every-replay sector set).
// Vector rows go back to default __ldg so they don't compete for the
// evict_last partition. Output stores remain streaming (.cs).
__global__ __launch_bounds__(128) void encoder_kernel(
    const int*    __restrict__ tokens,    // [N_TOKENS]
    const float4* __restrict__ vectors4,  // [N_PRE * 75]
    const float*  __restrict__ W,         // [HIDDEN, IN_SIZE]
    const float4* __restrict__ b4,        // [32]
    float4*       __restrict__ out4)      // [N_TOKENS * 107]
{
    const int t   = blockIdx.x;
    const int tid = threadIdx.x;
    const int tok = __ldg(&tokens[t]);        // tiny, broadcast

    float4* orow = out4 + (size_t)t * (OUT_DIM / 4);

    if (tok < N_PRE) {
        const float4* vrow = vectors4 + (size_t)tok * (VEC_DIM / 4);
        if (tid < 75) {
            float4 v = __ldg(&vrow[tid]);          // default policy
            stg_cs_f128(&orow[tid], v);
        }
        if (tid < 32) {
            stg_cs_f128(&orow[75 + tid], __ldg(&b4[tid]));
        }
    } else {
        const float4 z = make_float4(0.f, 0.f, 0.f, 0.f);
        if (tid < 75) stg_cs_f128(&orow[tid], z);
        if (tid < 32) {
            const uint64_t pol = mk_policy_evict_last();
            const int c = tok - N_PRE;
            const float* Wc = W + c + (size_t)(4 * tid) * IN_SIZE;
            // 4 independent pinned gathers (MLP=4), then one vectorized store
            float w0 = ldg_el_f32(Wc, pol);
            float w1 = ldg_el_f32(Wc + (size_t)IN_SIZE, pol);
            float w2 = ldg_el_f32(Wc + (size_t)2 * IN_SIZE, pol);
            float w3 = ldg_el_f32(Wc + (size_t)3 * IN_SIZE, pol);
            float4 bb = __ldg(&b4[tid]);
            float4 h = make_float4(bb.x + w0, bb.y + w1, bb.z + w2, bb.w + w3);
            stg_cs_f128(&orow[75 + tid], h);
        }
    }
}

extern "C" void kernel_launch(void* const* d_in, const int* in_sizes, int n_in,
                              void* d_out, int out_size)
{
    // metadata order: tokens (int32), vectors (f32), W (f32), b (f32)
    const int*    tokens  = (const int*)   d_in[0];
    const float4* vectors = (const float4*)d_in[1];
    const float*  W       = (const float*) d_in[2];
    const float4* b       = (const float4*)d_in[3];
    float4*       out     = (float4*)      d_out;

    encoder_kernel<<<N_TOKENS, 128>>>(tokens, vectors, W, b, out);
}